// round 1
// baseline (speedup 1.0000x reference)
#include <cuda_runtime.h>
#include <cuda_bf16.h>
#include <math.h>

// Problem constants
#define SEQ   2048
#define DM    2048
#define KVD   512     // NUM_GROUPS * HEAD_DIM = 8*64
#define HD    64
#define NHEAD 32

// Scratch (device globals — no allocation allowed)
__device__ float g_q[SEQ * DM];      // 16 MB
__device__ float g_k[SEQ * KVD];     // 4 MB
__device__ float g_v[SEQ * KVD];     // 4 MB
__device__ float g_attn[SEQ * DM];   // 16 MB

// ---------------------------------------------------------------------------
// SGEMM: C[M,N] = A[M,K] @ B[K,N], row-major, fp32.
// 128x128 block tile, BK=8, 256 threads, 8x8 microtile per thread.
// ---------------------------------------------------------------------------
__global__ __launch_bounds__(256) void sgemm_kernel(
    const float* __restrict__ A, const float* __restrict__ B,
    float* __restrict__ C, int M, int N, int K)
{
    __shared__ float As[8][128];
    __shared__ float Bs[8][128];

    const int tid = threadIdx.x;
    const int tx  = tid & 15;       // 0..15
    const int ty  = tid >> 4;       // 0..15
    const int row0 = blockIdx.y * 128;
    const int col0 = blockIdx.x * 128;

    // A load mapping: 128 rows x 8 cols, float4 along K
    const int aRow = tid >> 1;            // 0..127
    const int aCol = (tid & 1) * 4;       // 0 or 4
    // B load mapping: 8 rows x 128 cols, float4 along N
    const int bRow = tid >> 5;            // 0..7
    const int bCol = (tid & 31) * 4;      // 0..124

    const float* Aptr = A + (size_t)(row0 + aRow) * K + aCol;
    const float* Bptr = B + (size_t)bRow * N + col0 + bCol;

    float acc[8][8];
    #pragma unroll
    for (int i = 0; i < 8; i++)
        #pragma unroll
        for (int j = 0; j < 8; j++) acc[i][j] = 0.0f;

    for (int kk = 0; kk < K; kk += 8) {
        float4 av = *(const float4*)(Aptr + kk);
        float4 bv = *(const float4*)(Bptr + (size_t)kk * N);
        __syncthreads();   // previous tile consumed
        As[aCol + 0][aRow] = av.x;
        As[aCol + 1][aRow] = av.y;
        As[aCol + 2][aRow] = av.z;
        As[aCol + 3][aRow] = av.w;
        *(float4*)&Bs[bRow][bCol] = bv;
        __syncthreads();

        #pragma unroll
        for (int k = 0; k < 8; k++) {
            float4 a0 = *(const float4*)&As[k][ty * 8];
            float4 a1 = *(const float4*)&As[k][ty * 8 + 4];
            float4 b0 = *(const float4*)&Bs[k][tx * 8];
            float4 b1 = *(const float4*)&Bs[k][tx * 8 + 4];
            float a[8] = {a0.x, a0.y, a0.z, a0.w, a1.x, a1.y, a1.z, a1.w};
            float b[8] = {b0.x, b0.y, b0.z, b0.w, b1.x, b1.y, b1.z, b1.w};
            #pragma unroll
            for (int i = 0; i < 8; i++)
                #pragma unroll
                for (int j = 0; j < 8; j++)
                    acc[i][j] = fmaf(a[i], b[j], acc[i][j]);
        }
    }

    #pragma unroll
    for (int i = 0; i < 8; i++) {
        int r = row0 + ty * 8 + i;
        float* crow = C + (size_t)r * N + col0 + tx * 8;
        float4 o0 = make_float4(acc[i][0], acc[i][1], acc[i][2], acc[i][3]);
        float4 o1 = make_float4(acc[i][4], acc[i][5], acc[i][6], acc[i][7]);
        ((float4*)crow)[0] = o0;
        ((float4*)crow)[1] = o1;
    }
}

// ---------------------------------------------------------------------------
// Flash-style GQA attention.
// grid = (SEQ/128, NHEAD), block = 128 threads.
// Each thread owns one query row: q-row in registers, online softmax,
// 64-float accumulator in registers. K/V tiles (32x64) staged in smem and
// read via broadcast float4 loads.
// ---------------------------------------------------------------------------
#define QT 128
#define KT 32

__global__ __launch_bounds__(128) void attn_kernel(
    const float* __restrict__ q, const float* __restrict__ k,
    const float* __restrict__ v, float* __restrict__ o)
{
    __shared__ float Qs[QT][HD];   // 32 KB
    __shared__ float Ks[KT][HD];   // 8 KB
    __shared__ float Vs[KT][HD];   // 8 KB

    const int tid = threadIdx.x;
    const int qt  = blockIdx.x;
    const int h   = blockIdx.y;
    const int g   = h >> 2;            // 4 heads per group
    const int q0  = qt * QT;

    // Cooperative, coalesced Q tile load
    for (int i = tid; i < QT * HD; i += 128) {
        int r = i >> 6, c = i & 63;
        Qs[r][c] = q[(size_t)(q0 + r) * DM + h * HD + c];
    }
    __syncthreads();

    const float scale = 0.125f;  // 1/sqrt(64)
    float qreg[HD];
    #pragma unroll
    for (int c = 0; c < HD; c++) qreg[c] = Qs[tid][c] * scale;

    float acc[HD];
    #pragma unroll
    for (int c = 0; c < HD; c++) acc[c] = 0.0f;
    float m = -INFINITY, l = 0.0f;

    for (int kt = 0; kt < SEQ; kt += KT) {
        __syncthreads();   // prior tile fully consumed
        for (int i = tid; i < KT * HD; i += 128) {
            int r = i >> 6, c = i & 63;
            Ks[r][c] = k[(size_t)(kt + r) * KVD + g * HD + c];
            Vs[r][c] = v[(size_t)(kt + r) * KVD + g * HD + c];
        }
        __syncthreads();

        float s[KT];
        #pragma unroll
        for (int j = 0; j < KT; j++) {
            const float4* kr = (const float4*)Ks[j];
            float sum = 0.0f;
            #pragma unroll
            for (int c4 = 0; c4 < HD / 4; c4++) {
                float4 kv = kr[c4];
                sum = fmaf(qreg[c4*4+0], kv.x, sum);
                sum = fmaf(qreg[c4*4+1], kv.y, sum);
                sum = fmaf(qreg[c4*4+2], kv.z, sum);
                sum = fmaf(qreg[c4*4+3], kv.w, sum);
            }
            s[j] = sum;
        }

        float mt = m;
        #pragma unroll
        for (int j = 0; j < KT; j++) mt = fmaxf(mt, s[j]);
        float factor = __expf(m - mt);
        m = mt;
        l *= factor;
        #pragma unroll
        for (int c = 0; c < HD; c++) acc[c] *= factor;

        #pragma unroll
        for (int j = 0; j < KT; j++) {
            s[j] = __expf(s[j] - mt);   // reuse s[] as p[]
            l += s[j];
        }

        #pragma unroll
        for (int j = 0; j < KT; j++) {
            const float4* vr = (const float4*)Vs[j];
            float pj = s[j];
            #pragma unroll
            for (int c4 = 0; c4 < HD / 4; c4++) {
                float4 vv = vr[c4];
                acc[c4*4+0] = fmaf(pj, vv.x, acc[c4*4+0]);
                acc[c4*4+1] = fmaf(pj, vv.y, acc[c4*4+1]);
                acc[c4*4+2] = fmaf(pj, vv.z, acc[c4*4+2]);
                acc[c4*4+3] = fmaf(pj, vv.w, acc[c4*4+3]);
            }
        }
    }

    float inv = 1.0f / l;
    float* orow = o + (size_t)(q0 + tid) * DM + h * HD;
    #pragma unroll
    for (int c4 = 0; c4 < HD / 4; c4++) {
        float4 ov = make_float4(acc[c4*4+0] * inv, acc[c4*4+1] * inv,
                                acc[c4*4+2] * inv, acc[c4*4+3] * inv);
        ((float4*)orow)[c4] = ov;
    }
}

// ---------------------------------------------------------------------------
// Launch
// ---------------------------------------------------------------------------
extern "C" void kernel_launch(void* const* d_in, const int* in_sizes, int n_in,
                              void* d_out, int out_size)
{
    const float* x   = (const float*)d_in[0];
    const float* w_q = (const float*)d_in[1];
    const float* w_k = (const float*)d_in[2];
    const float* w_v = (const float*)d_in[3];
    const float* w_o = (const float*)d_in[4];
    float* out = (float*)d_out;

    float *qb, *kb, *vb, *ab;
    cudaGetSymbolAddress((void**)&qb, g_q);
    cudaGetSymbolAddress((void**)&kb, g_k);
    cudaGetSymbolAddress((void**)&vb, g_v);
    cudaGetSymbolAddress((void**)&ab, g_attn);

    dim3 gridQ(DM / 128, SEQ / 128);    // 16x16
    dim3 gridKV(KVD / 128, SEQ / 128);  // 4x16

    sgemm_kernel<<<gridQ, 256>>>(x, w_q, qb, SEQ, DM, DM);
    sgemm_kernel<<<gridKV, 256>>>(x, w_k, kb, SEQ, KVD, DM);
    sgemm_kernel<<<gridKV, 256>>>(x, w_v, vb, SEQ, KVD, DM);

    dim3 gridA(SEQ / QT, NHEAD);        // 16x32
    attn_kernel<<<gridA, 128>>>(qb, kb, vb, ab);

    sgemm_kernel<<<gridQ, 256>>>(ab, w_o, out, SEQ, DM, DM);
}

// round 2
// speedup vs baseline: 1.5356x; 1.5356x over previous
#include <cuda_runtime.h>
#include <cuda_bf16.h>
#include <math.h>
#include <stdint.h>

// Problem constants
#define SEQ   2048
#define DM    2048
#define KVD   512     // NUM_GROUPS * HEAD_DIM = 8*64
#define HD    64
#define NHEAD 32

// Scratch (device globals — no allocation allowed)
__device__ float g_q[SEQ * DM];      // 16 MB
__device__ float g_k[SEQ * KVD];     // 4 MB
__device__ float g_v[SEQ * KVD];     // 4 MB
__device__ float g_attn[SEQ * DM];   // 16 MB

// ---------------------------------------------------------------------------
// tf32 helpers
// ---------------------------------------------------------------------------
__device__ __forceinline__ float t32(float x) {
    asm("cvt.rna.tf32.f32 %0, %1;" : "=f"(x) : "f"(x));
    return x;
}

__device__ __forceinline__ void mma_tf32(float* c, const uint32_t* a, const uint32_t* b) {
    asm volatile(
        "mma.sync.aligned.m16n8k8.row.col.f32.tf32.tf32.f32 "
        "{%0,%1,%2,%3}, {%4,%5,%6,%7}, {%8,%9}, {%0,%1,%2,%3};"
        : "+f"(c[0]), "+f"(c[1]), "+f"(c[2]), "+f"(c[3])
        : "r"(a[0]), "r"(a[1]), "r"(a[2]), "r"(a[3]),
          "r"(b[0]), "r"(b[1]));
}

// ---------------------------------------------------------------------------
// tf32 tensor-core GEMM: C[M,N] = A[M,K] @ B[K,N], row-major fp32 in/out.
// 128x128 block tile, BK=32, 256 threads = 8 warps (2x4), warp tile 64x32.
// Each warp: 4 m-atoms x 4 n-atoms of m16n8k8.
// ---------------------------------------------------------------------------
__global__ __launch_bounds__(256) void sgemm_tf32(
    const float* __restrict__ A, const float* __restrict__ B,
    float* __restrict__ C, int M, int N, int K)
{
    __shared__ float As[32][132];   // [k][m], padded
    __shared__ float Bs[32][132];   // [k][n], padded

    const int tid  = threadIdx.x;
    const int lane = tid & 31;
    const int wid  = tid >> 5;
    const int warpRow = (wid >> 2) * 64;   // 0 or 64
    const int warpCol = (wid & 3) * 32;    // 0..96
    const int gid  = lane >> 2;            // 0..7
    const int ctid = lane & 3;             // 0..3
    const int row0 = blockIdx.y * 128;
    const int col0 = blockIdx.x * 128;

    // Global load mappings
    const int aRow = tid >> 3;             // 0..31 (4 passes of +32)
    const int aCol = (tid & 7) * 4;        // 0..28 (float4 along K)
    const int bRow = tid >> 5;             // 0..7  (4 passes of +8)
    const int bCol = (tid & 31) * 4;       // 0..124 (float4 along N)

    const float* Ap = A + (size_t)(row0 + aRow) * K + aCol;
    const float* Bp = B + (size_t)bRow * N + col0 + bCol;

    float4 ar[4], br[4];
    #pragma unroll
    for (int r = 0; r < 4; r++) ar[r] = *(const float4*)(Ap + (size_t)(r * 32) * K);
    #pragma unroll
    for (int r = 0; r < 4; r++) br[r] = *(const float4*)(Bp + (size_t)(r * 8) * N);

    float acc[4][4][4];
    #pragma unroll
    for (int im = 0; im < 4; im++)
        #pragma unroll
        for (int in = 0; in < 4; in++)
            #pragma unroll
            for (int r = 0; r < 4; r++) acc[im][in][r] = 0.0f;

    for (int kk = 0; kk < K; kk += 32) {
        // Stage current tile (with tf32 rounding)
        #pragma unroll
        for (int r = 0; r < 4; r++) {
            int rr = aRow + r * 32;
            As[aCol + 0][rr] = t32(ar[r].x);
            As[aCol + 1][rr] = t32(ar[r].y);
            As[aCol + 2][rr] = t32(ar[r].z);
            As[aCol + 3][rr] = t32(ar[r].w);
        }
        #pragma unroll
        for (int r = 0; r < 4; r++) {
            int rr = bRow + r * 8;
            Bs[rr][bCol + 0] = t32(br[r].x);
            Bs[rr][bCol + 1] = t32(br[r].y);
            Bs[rr][bCol + 2] = t32(br[r].z);
            Bs[rr][bCol + 3] = t32(br[r].w);
        }
        __syncthreads();

        // Prefetch next tile
        if (kk + 32 < K) {
            #pragma unroll
            for (int r = 0; r < 4; r++) ar[r] = *(const float4*)(Ap + kk + 32 + (size_t)(r * 32) * K);
            #pragma unroll
            for (int r = 0; r < 4; r++) br[r] = *(const float4*)(Bp + (size_t)(kk + 32 + r * 8) * N);
        }

        // 4 k-steps of k8
        #pragma unroll
        for (int ks = 0; ks < 4; ks++) {
            uint32_t af[4][4];
            uint32_t bf[4][2];
            #pragma unroll
            for (int im = 0; im < 4; im++) {
                int r = warpRow + im * 16 + gid;
                af[im][0] = __float_as_uint(As[ks * 8 + ctid][r]);
                af[im][1] = __float_as_uint(As[ks * 8 + ctid][r + 8]);
                af[im][2] = __float_as_uint(As[ks * 8 + ctid + 4][r]);
                af[im][3] = __float_as_uint(As[ks * 8 + ctid + 4][r + 8]);
            }
            #pragma unroll
            for (int in = 0; in < 4; in++) {
                int c = warpCol + in * 8 + gid;
                bf[in][0] = __float_as_uint(Bs[ks * 8 + ctid][c]);
                bf[in][1] = __float_as_uint(Bs[ks * 8 + ctid + 4][c]);
            }
            #pragma unroll
            for (int im = 0; im < 4; im++)
                #pragma unroll
                for (int in = 0; in < 4; in++)
                    mma_tf32(acc[im][in], af[im], bf[in]);
        }
        __syncthreads();
    }

    // Epilogue: c0=C[gid][2ctid], c1=+1, c2=C[gid+8][2ctid], c3=+1
    #pragma unroll
    for (int im = 0; im < 4; im++) {
        #pragma unroll
        for (int in = 0; in < 4; in++) {
            int r = row0 + warpRow + im * 16 + gid;
            int c = col0 + warpCol + in * 8 + 2 * ctid;
            float2* p0 = (float2*)(C + (size_t)r * N + c);
            float2* p1 = (float2*)(C + (size_t)(r + 8) * N + c);
            *p0 = make_float2(acc[im][in][0], acc[im][in][1]);
            *p1 = make_float2(acc[im][in][2], acc[im][in][3]);
        }
    }
}

// ---------------------------------------------------------------------------
// Flash-style GQA attention (fp32 FFMA, unchanged from passing round 1).
// grid = (SEQ/128, NHEAD), block = 128 threads.
// ---------------------------------------------------------------------------
#define QT 128
#define KT 32

__global__ __launch_bounds__(128) void attn_kernel(
    const float* __restrict__ q, const float* __restrict__ k,
    const float* __restrict__ v, float* __restrict__ o)
{
    __shared__ float Qs[QT][HD];   // 32 KB
    __shared__ float Ks[KT][HD];   // 8 KB
    __shared__ float Vs[KT][HD];   // 8 KB

    const int tid = threadIdx.x;
    const int qt  = blockIdx.x;
    const int h   = blockIdx.y;
    const int g   = h >> 2;            // 4 heads per group
    const int q0  = qt * QT;

    for (int i = tid; i < QT * HD; i += 128) {
        int r = i >> 6, c = i & 63;
        Qs[r][c] = q[(size_t)(q0 + r) * DM + h * HD + c];
    }
    __syncthreads();

    const float scale = 0.125f;  // 1/sqrt(64)
    float qreg[HD];
    #pragma unroll
    for (int c = 0; c < HD; c++) qreg[c] = Qs[tid][c] * scale;

    float acc[HD];
    #pragma unroll
    for (int c = 0; c < HD; c++) acc[c] = 0.0f;
    float m = -INFINITY, l = 0.0f;

    for (int kt = 0; kt < SEQ; kt += KT) {
        __syncthreads();
        for (int i = tid; i < KT * HD; i += 128) {
            int r = i >> 6, c = i & 63;
            Ks[r][c] = k[(size_t)(kt + r) * KVD + g * HD + c];
            Vs[r][c] = v[(size_t)(kt + r) * KVD + g * HD + c];
        }
        __syncthreads();

        float s[KT];
        #pragma unroll
        for (int j = 0; j < KT; j++) {
            const float4* kr = (const float4*)Ks[j];
            float sum = 0.0f;
            #pragma unroll
            for (int c4 = 0; c4 < HD / 4; c4++) {
                float4 kv = kr[c4];
                sum = fmaf(qreg[c4*4+0], kv.x, sum);
                sum = fmaf(qreg[c4*4+1], kv.y, sum);
                sum = fmaf(qreg[c4*4+2], kv.z, sum);
                sum = fmaf(qreg[c4*4+3], kv.w, sum);
            }
            s[j] = sum;
        }

        float mt = m;
        #pragma unroll
        for (int j = 0; j < KT; j++) mt = fmaxf(mt, s[j]);
        float factor = __expf(m - mt);
        m = mt;
        l *= factor;
        #pragma unroll
        for (int c = 0; c < HD; c++) acc[c] *= factor;

        #pragma unroll
        for (int j = 0; j < KT; j++) {
            s[j] = __expf(s[j] - mt);
            l += s[j];
        }

        #pragma unroll
        for (int j = 0; j < KT; j++) {
            const float4* vr = (const float4*)Vs[j];
            float pj = s[j];
            #pragma unroll
            for (int c4 = 0; c4 < HD / 4; c4++) {
                float4 vv = vr[c4];
                acc[c4*4+0] = fmaf(pj, vv.x, acc[c4*4+0]);
                acc[c4*4+1] = fmaf(pj, vv.y, acc[c4*4+1]);
                acc[c4*4+2] = fmaf(pj, vv.z, acc[c4*4+2]);
                acc[c4*4+3] = fmaf(pj, vv.w, acc[c4*4+3]);
            }
        }
    }

    float inv = 1.0f / l;
    float* orow = o + (size_t)(q0 + tid) * DM + h * HD;
    #pragma unroll
    for (int c4 = 0; c4 < HD / 4; c4++) {
        float4 ov = make_float4(acc[c4*4+0] * inv, acc[c4*4+1] * inv,
                                acc[c4*4+2] * inv, acc[c4*4+3] * inv);
        ((float4*)orow)[c4] = ov;
    }
}

// ---------------------------------------------------------------------------
// Launch
// ---------------------------------------------------------------------------
extern "C" void kernel_launch(void* const* d_in, const int* in_sizes, int n_in,
                              void* d_out, int out_size)
{
    const float* x   = (const float*)d_in[0];
    const float* w_q = (const float*)d_in[1];
    const float* w_k = (const float*)d_in[2];
    const float* w_v = (const float*)d_in[3];
    const float* w_o = (const float*)d_in[4];
    float* out = (float*)d_out;

    float *qb, *kb, *vb, *ab;
    cudaGetSymbolAddress((void**)&qb, g_q);
    cudaGetSymbolAddress((void**)&kb, g_k);
    cudaGetSymbolAddress((void**)&vb, g_v);
    cudaGetSymbolAddress((void**)&ab, g_attn);

    dim3 gridQ(DM / 128, SEQ / 128);    // 16x16
    dim3 gridKV(KVD / 128, SEQ / 128);  // 4x16

    sgemm_tf32<<<gridQ, 256>>>(x, w_q, qb, SEQ, DM, DM);
    sgemm_tf32<<<gridKV, 256>>>(x, w_k, kb, SEQ, KVD, DM);
    sgemm_tf32<<<gridKV, 256>>>(x, w_v, vb, SEQ, KVD, DM);

    dim3 gridA(SEQ / QT, NHEAD);        // 16x32
    attn_kernel<<<gridA, 128>>>(qb, kb, vb, ab);

    sgemm_tf32<<<gridQ, 256>>>(ab, w_o, out, SEQ, DM, DM);
}

// round 3
// speedup vs baseline: 3.2638x; 2.1255x over previous
#include <cuda_runtime.h>
#include <cuda_bf16.h>
#include <math.h>
#include <stdint.h>

// Problem constants
#define SEQ   2048
#define DM    2048
#define KVD   512     // NUM_GROUPS * HEAD_DIM = 8*64
#define HD    64
#define NHEAD 32

// Scratch (device globals — no allocation allowed)
__device__ float g_q[SEQ * DM];      // 16 MB
__device__ float g_k[SEQ * KVD];     // 4 MB
__device__ float g_v[SEQ * KVD];     // 4 MB
__device__ float g_attn[SEQ * DM];   // 16 MB

// ---------------------------------------------------------------------------
// tf32 helpers
// ---------------------------------------------------------------------------
__device__ __forceinline__ float t32(float x) {
    asm("cvt.rna.tf32.f32 %0, %1;" : "=f"(x) : "f"(x));
    return x;
}

__device__ __forceinline__ void mma_tf32(float* c, const uint32_t* a, const uint32_t* b) {
    asm volatile(
        "mma.sync.aligned.m16n8k8.row.col.f32.tf32.tf32.f32 "
        "{%0,%1,%2,%3}, {%4,%5,%6,%7}, {%8,%9}, {%0,%1,%2,%3};"
        : "+f"(c[0]), "+f"(c[1]), "+f"(c[2]), "+f"(c[3])
        : "r"(a[0]), "r"(a[1]), "r"(a[2]), "r"(a[3]),
          "r"(b[0]), "r"(b[1]));
}

// ---------------------------------------------------------------------------
// tf32 tensor-core GEMM: C[M,N] = A[M,K] @ B[K,N], row-major fp32 in/out.
// 128x128 block tile, BK=32, 256 threads = 8 warps (2x4), warp tile 64x32.
// ---------------------------------------------------------------------------
__global__ __launch_bounds__(256) void sgemm_tf32(
    const float* __restrict__ A, const float* __restrict__ B,
    float* __restrict__ C, int M, int N, int K)
{
    __shared__ float As[32][132];   // [k][m], padded
    __shared__ float Bs[32][132];   // [k][n], padded

    const int tid  = threadIdx.x;
    const int lane = tid & 31;
    const int wid  = tid >> 5;
    const int warpRow = (wid >> 2) * 64;   // 0 or 64
    const int warpCol = (wid & 3) * 32;    // 0..96
    const int gid  = lane >> 2;            // 0..7
    const int ctid = lane & 3;             // 0..3
    const int row0 = blockIdx.y * 128;
    const int col0 = blockIdx.x * 128;

    const int aRow = tid >> 3;             // 0..31
    const int aCol = (tid & 7) * 4;        // 0..28
    const int bRow = tid >> 5;             // 0..7
    const int bCol = (tid & 31) * 4;       // 0..124

    const float* Ap = A + (size_t)(row0 + aRow) * K + aCol;
    const float* Bp = B + (size_t)bRow * N + col0 + bCol;

    float4 ar[4], br[4];
    #pragma unroll
    for (int r = 0; r < 4; r++) ar[r] = *(const float4*)(Ap + (size_t)(r * 32) * K);
    #pragma unroll
    for (int r = 0; r < 4; r++) br[r] = *(const float4*)(Bp + (size_t)(r * 8) * N);

    float acc[4][4][4];
    #pragma unroll
    for (int im = 0; im < 4; im++)
        #pragma unroll
        for (int in = 0; in < 4; in++)
            #pragma unroll
            for (int r = 0; r < 4; r++) acc[im][in][r] = 0.0f;

    for (int kk = 0; kk < K; kk += 32) {
        #pragma unroll
        for (int r = 0; r < 4; r++) {
            int rr = aRow + r * 32;
            As[aCol + 0][rr] = t32(ar[r].x);
            As[aCol + 1][rr] = t32(ar[r].y);
            As[aCol + 2][rr] = t32(ar[r].z);
            As[aCol + 3][rr] = t32(ar[r].w);
        }
        #pragma unroll
        for (int r = 0; r < 4; r++) {
            int rr = bRow + r * 8;
            Bs[rr][bCol + 0] = t32(br[r].x);
            Bs[rr][bCol + 1] = t32(br[r].y);
            Bs[rr][bCol + 2] = t32(br[r].z);
            Bs[rr][bCol + 3] = t32(br[r].w);
        }
        __syncthreads();

        if (kk + 32 < K) {
            #pragma unroll
            for (int r = 0; r < 4; r++) ar[r] = *(const float4*)(Ap + kk + 32 + (size_t)(r * 32) * K);
            #pragma unroll
            for (int r = 0; r < 4; r++) br[r] = *(const float4*)(Bp + (size_t)(kk + 32 + r * 8) * N);
        }

        #pragma unroll
        for (int ks = 0; ks < 4; ks++) {
            uint32_t af[4][4];
            uint32_t bf[4][2];
            #pragma unroll
            for (int im = 0; im < 4; im++) {
                int r = warpRow + im * 16 + gid;
                af[im][0] = __float_as_uint(As[ks * 8 + ctid][r]);
                af[im][1] = __float_as_uint(As[ks * 8 + ctid][r + 8]);
                af[im][2] = __float_as_uint(As[ks * 8 + ctid + 4][r]);
                af[im][3] = __float_as_uint(As[ks * 8 + ctid + 4][r + 8]);
            }
            #pragma unroll
            for (int in = 0; in < 4; in++) {
                int c = warpCol + in * 8 + gid;
                bf[in][0] = __float_as_uint(Bs[ks * 8 + ctid][c]);
                bf[in][1] = __float_as_uint(Bs[ks * 8 + ctid + 4][c]);
            }
            #pragma unroll
            for (int im = 0; im < 4; im++)
                #pragma unroll
                for (int in = 0; in < 4; in++)
                    mma_tf32(acc[im][in], af[im], bf[in]);
        }
        __syncthreads();
    }

    #pragma unroll
    for (int im = 0; im < 4; im++) {
        #pragma unroll
        for (int in = 0; in < 4; in++) {
            int r = row0 + warpRow + im * 16 + gid;
            int c = col0 + warpCol + in * 8 + 2 * ctid;
            float2* p0 = (float2*)(C + (size_t)r * N + c);
            float2* p1 = (float2*)(C + (size_t)(r + 8) * N + c);
            *p0 = make_float2(acc[im][in][0], acc[im][in][1]);
            *p1 = make_float2(acc[im][in][2], acc[im][in][3]);
        }
    }
}

// ---------------------------------------------------------------------------
// Tensor-core flash attention (tf32 mma, online softmax).
// grid = (SEQ/128, NHEAD), block = 256 threads = 8 warps x 16 q-rows.
// K-tile = 32 keys per iteration.
// Fragment mappings identical to the validated sgemm_tf32 kernel.
// ---------------------------------------------------------------------------
#define KT2 32

__global__ __launch_bounds__(256) void attn_mma(
    const float* __restrict__ q, const float* __restrict__ k,
    const float* __restrict__ v, float* __restrict__ out)
{
    __shared__ float Ks[KT2][68];    // [key][d], stride 68: b-frag conflict-free
    __shared__ float Vs[KT2][72];    // [key][d], stride 72: b-frag conflict-free
    __shared__ float Ps[128][36];    // [qrow][key], stride 36: a-frag conflict-free

    const int tid  = threadIdx.x;
    const int lane = tid & 31;
    const int w    = tid >> 5;         // warp 0..7
    const int gid  = lane >> 2;        // 0..7
    const int ctid = lane & 3;         // 0..3
    const int h    = blockIdx.y;
    const int g    = h >> 2;           // 4 heads per KV group
    const int q0   = blockIdx.x * 128;
    const int rowA = q0 + w * 16 + gid;   // global q row for slot0 (slot1 = +8)
    const int prow = w * 16 + gid;        // local P row

    // Q fragments: held in registers for whole kernel, scale folded in.
    const float scale = 0.125f;  // 1/sqrt(64)
    uint32_t aq[8][4];
    #pragma unroll
    for (int kf = 0; kf < 8; kf++) {
        const float* qp = q + (size_t)rowA * DM + h * HD + kf * 8 + ctid;
        aq[kf][0] = __float_as_uint(t32(qp[0] * scale));
        aq[kf][1] = __float_as_uint(t32(qp[(size_t)8 * DM] * scale));
        aq[kf][2] = __float_as_uint(t32(qp[4] * scale));
        aq[kf][3] = __float_as_uint(t32(qp[(size_t)8 * DM + 4] * scale));
    }

    float o_acc[8][4];
    #pragma unroll
    for (int in = 0; in < 8; in++)
        #pragma unroll
        for (int r = 0; r < 4; r++) o_acc[in][r] = 0.0f;
    float m0 = -INFINITY, m1 = -INFINITY, l0 = 0.0f, l1 = 0.0f;

    for (int kt = 0; kt < SEQ; kt += KT2) {
        __syncthreads();   // all warps done reading previous K/V tiles
        // Cooperative K/V tile load (32 keys x 64 d), tf32-rounded.
        #pragma unroll
        for (int t = 0; t < 2; t++) {
            int idx = tid + t * 256;          // 0..511 float4 slots
            int r = idx >> 4, c4 = idx & 15;
            float4 kv4 = *(const float4*)(k + (size_t)(kt + r) * KVD + g * HD + c4 * 4);
            float4 vv4 = *(const float4*)(v + (size_t)(kt + r) * KVD + g * HD + c4 * 4);
            *(float4*)&Ks[r][c4 * 4] = make_float4(t32(kv4.x), t32(kv4.y), t32(kv4.z), t32(kv4.w));
            *(float4*)&Vs[r][c4 * 4] = make_float4(t32(vv4.x), t32(vv4.y), t32(vv4.z), t32(vv4.w));
        }
        __syncthreads();

        // S = Q @ K^T : 4 n-atoms (32 keys) x 8 k-frags (d=64)
        float s[4][4];
        #pragma unroll
        for (int in = 0; in < 4; in++)
            #pragma unroll
            for (int r = 0; r < 4; r++) s[in][r] = 0.0f;

        #pragma unroll
        for (int in = 0; in < 4; in++) {
            #pragma unroll
            for (int kf = 0; kf < 8; kf++) {
                uint32_t b[2];
                b[0] = __float_as_uint(Ks[in * 8 + gid][kf * 8 + ctid]);
                b[1] = __float_as_uint(Ks[in * 8 + gid][kf * 8 + ctid + 4]);
                mma_tf32(s[in], aq[kf], b);
            }
        }

        // Online softmax. slot0 = row gid (c0,c1), slot1 = row gid+8 (c2,c3).
        float mx0 = -INFINITY, mx1 = -INFINITY;
        #pragma unroll
        for (int in = 0; in < 4; in++) {
            mx0 = fmaxf(mx0, fmaxf(s[in][0], s[in][1]));
            mx1 = fmaxf(mx1, fmaxf(s[in][2], s[in][3]));
        }
        mx0 = fmaxf(mx0, __shfl_xor_sync(0xffffffffu, mx0, 1));
        mx0 = fmaxf(mx0, __shfl_xor_sync(0xffffffffu, mx0, 2));
        mx1 = fmaxf(mx1, __shfl_xor_sync(0xffffffffu, mx1, 1));
        mx1 = fmaxf(mx1, __shfl_xor_sync(0xffffffffu, mx1, 2));

        float mt0 = fmaxf(m0, mx0), mt1 = fmaxf(m1, mx1);
        float f0 = __expf(m0 - mt0), f1 = __expf(m1 - mt1);
        m0 = mt0; m1 = mt1;

        float rs0 = 0.0f, rs1 = 0.0f;
        #pragma unroll
        for (int in = 0; in < 4; in++) {
            s[in][0] = __expf(s[in][0] - mt0);
            s[in][1] = __expf(s[in][1] - mt0);
            s[in][2] = __expf(s[in][2] - mt1);
            s[in][3] = __expf(s[in][3] - mt1);
            rs0 += s[in][0] + s[in][1];
            rs1 += s[in][2] + s[in][3];
        }
        rs0 += __shfl_xor_sync(0xffffffffu, rs0, 1);
        rs0 += __shfl_xor_sync(0xffffffffu, rs0, 2);
        rs1 += __shfl_xor_sync(0xffffffffu, rs1, 1);
        rs1 += __shfl_xor_sync(0xffffffffu, rs1, 2);
        l0 = l0 * f0 + rs0;
        l1 = l1 * f1 + rs1;

        #pragma unroll
        for (int in = 0; in < 8; in++) {
            o_acc[in][0] *= f0;
            o_acc[in][1] *= f0;
            o_acc[in][2] *= f1;
            o_acc[in][3] *= f1;
        }

        // Re-layout P: C-fragment -> smem -> A-fragment (warp-private rows).
        #pragma unroll
        for (int in = 0; in < 4; in++) {
            *(float2*)&Ps[prow][in * 8 + 2 * ctid] =
                make_float2(t32(s[in][0]), t32(s[in][1]));
            *(float2*)&Ps[prow + 8][in * 8 + 2 * ctid] =
                make_float2(t32(s[in][2]), t32(s[in][3]));
        }
        __syncwarp();

        // O += P @ V : 4 k-frags (32 keys) x 8 n-atoms (d=64)
        #pragma unroll
        for (int kf = 0; kf < 4; kf++) {
            uint32_t ap[4];
            ap[0] = __float_as_uint(Ps[prow][kf * 8 + ctid]);
            ap[1] = __float_as_uint(Ps[prow + 8][kf * 8 + ctid]);
            ap[2] = __float_as_uint(Ps[prow][kf * 8 + ctid + 4]);
            ap[3] = __float_as_uint(Ps[prow + 8][kf * 8 + ctid + 4]);
            #pragma unroll
            for (int in = 0; in < 8; in++) {
                uint32_t b[2];
                b[0] = __float_as_uint(Vs[kf * 8 + ctid][in * 8 + gid]);
                b[1] = __float_as_uint(Vs[kf * 8 + ctid + 4][in * 8 + gid]);
                mma_tf32(o_acc[in], ap, b);
            }
        }
        __syncwarp();
    }

    // Epilogue
    float inv0 = 1.0f / l0, inv1 = 1.0f / l1;
    #pragma unroll
    for (int in = 0; in < 8; in++) {
        float* p0 = out + (size_t)rowA * DM + h * HD + in * 8 + 2 * ctid;
        float* p1 = out + (size_t)(rowA + 8) * DM + h * HD + in * 8 + 2 * ctid;
        *(float2*)p0 = make_float2(o_acc[in][0] * inv0, o_acc[in][1] * inv0);
        *(float2*)p1 = make_float2(o_acc[in][2] * inv1, o_acc[in][3] * inv1);
    }
}

// ---------------------------------------------------------------------------
// Launch
// ---------------------------------------------------------------------------
extern "C" void kernel_launch(void* const* d_in, const int* in_sizes, int n_in,
                              void* d_out, int out_size)
{
    const float* x   = (const float*)d_in[0];
    const float* w_q = (const float*)d_in[1];
    const float* w_k = (const float*)d_in[2];
    const float* w_v = (const float*)d_in[3];
    const float* w_o = (const float*)d_in[4];
    float* out = (float*)d_out;

    float *qb, *kb, *vb, *ab;
    cudaGetSymbolAddress((void**)&qb, g_q);
    cudaGetSymbolAddress((void**)&kb, g_k);
    cudaGetSymbolAddress((void**)&vb, g_v);
    cudaGetSymbolAddress((void**)&ab, g_attn);

    dim3 gridQ(DM / 128, SEQ / 128);    // 16x16
    dim3 gridKV(KVD / 128, SEQ / 128);  // 4x16

    sgemm_tf32<<<gridQ, 256>>>(x, w_q, qb, SEQ, DM, DM);
    sgemm_tf32<<<gridKV, 256>>>(x, w_k, kb, SEQ, KVD, DM);
    sgemm_tf32<<<gridKV, 256>>>(x, w_v, vb, SEQ, KVD, DM);

    dim3 gridA(SEQ / 128, NHEAD);       // 16x32
    attn_mma<<<gridA, 256>>>(qb, kb, vb, ab);

    sgemm_tf32<<<gridQ, 256>>>(ab, w_o, out, SEQ, DM, DM);
}